// round 14
// baseline (speedup 1.0000x reference)
#include <cuda_runtime.h>
#include <cuda_bf16.h>
#include <cuda_fp16.h>
#include <math.h>
#include <stdint.h>

#define Bx 4
#define Nx 2048
#define DIMx 256
#define Hx 8
#define HDx 32
#define Fx 64
#define MTOT (Bx*Nx)
#define NT 32

// ------------------------- device scratch (no allocs) -----------------------
__device__ __nv_bfloat16 g_Xh[MTOT*DIMx];
__device__ __nv_bfloat16 g_Xl[MTOT*DIMx];
__device__ __nv_bfloat16 g_Wth[4*DIMx*DIMx];   // transposed weights [mode][n][k]
__device__ __nv_bfloat16 g_Wtl[4*DIMx*DIMx];
__device__ __half        g_Qf[Bx*Hx*Nx*Fx];     // fp16 features * sqrt(SCL2)
__device__ __half        g_Kf[Bx*Hx*Nx*Fx];
__device__ __half        g_Vtf[Bx*Hx*HDx*Nx];   // [bh][d][n], fp16
__device__ __nv_bfloat16 g_AOh[MTOT*DIMx];
__device__ __nv_bfloat16 g_AOl[MTOT*DIMx];

// ------------------------- helpers ------------------------------------------
__device__ __forceinline__ uint32_t smem_u32(const void* p) {
    uint32_t a;
    asm("{ .reg .u64 t; cvta.to.shared.u64 t, %1; cvt.u32.u64 %0, t; }" : "=r"(a) : "l"(p));
    return a;
}
__device__ __forceinline__ uint32_t packbf2(float lo, float hi) {
    uint32_t r;
    asm("cvt.rn.bf16x2.f32 %0, %1, %2;" : "=r"(r) : "f"(hi), "f"(lo));
    return r;
}
__device__ __forceinline__ void split2(float v0, float v1, uint32_t& hp, uint32_t& lp) {
    hp = packbf2(v0, v1);
    float h0 = __uint_as_float(hp << 16), h1 = __uint_as_float(hp & 0xffff0000u);
    lp = packbf2(v0 - h0, v1 - h1);
}
__device__ __forceinline__ uint32_t packh2(float lo, float hi) {
    uint32_t r;
    asm("cvt.rn.f16x2.f32 %0, %1, %2;" : "=r"(r) : "f"(hi), "f"(lo));
    return r;
}
__device__ __forceinline__ void ldsm4(uint32_t* r, uint32_t addr) {
    asm volatile("ldmatrix.sync.aligned.m8n8.x4.shared.b16 {%0,%1,%2,%3}, [%4];"
        : "=r"(r[0]), "=r"(r[1]), "=r"(r[2]), "=r"(r[3]) : "r"(addr));
}
__device__ __forceinline__ void mma_bf16(float* c, const uint32_t* a, const uint32_t* b) {
    asm volatile("mma.sync.aligned.m16n8k16.row.col.f32.bf16.bf16.f32 "
        "{%0,%1,%2,%3}, {%4,%5,%6,%7}, {%8,%9}, {%0,%1,%2,%3};"
        : "+f"(c[0]), "+f"(c[1]), "+f"(c[2]), "+f"(c[3])
        : "r"(a[0]), "r"(a[1]), "r"(a[2]), "r"(a[3]), "r"(b[0]), "r"(b[1]));
}
__device__ __forceinline__ void mma_fp16(float* c, const uint32_t* a, const uint32_t* b) {
    asm volatile("mma.sync.aligned.m16n8k16.row.col.f32.f16.f16.f32 "
        "{%0,%1,%2,%3}, {%4,%5,%6,%7}, {%8,%9}, {%0,%1,%2,%3};"
        : "+f"(c[0]), "+f"(c[1]), "+f"(c[2]), "+f"(c[3])
        : "r"(a[0]), "r"(a[1]), "r"(a[2]), "r"(a[3]), "r"(b[0]), "r"(b[1]));
}
__device__ __forceinline__ uint32_t sw128(uint32_t off) {
    return off ^ ((off >> 3) & 0x70);
}
__device__ __forceinline__ void cp16(uint32_t dst, const void* src) {
    asm volatile("cp.async.cg.shared.global [%0], [%1], 16;" :: "r"(dst), "l"(src) : "memory");
}
#define CP_COMMIT() asm volatile("cp.async.commit_group;" ::: "memory")

#define CFOLD 0.71420719f       /* sqrt((2/sqrt(32))*log2(e)) */
#define SM2H  6.4467223514f     /* 11.4*log2(e) - 10  (p scaled by 2^10) */

// ---------------------------------------------------------------------------
// Prep kernels
// ---------------------------------------------------------------------------
__global__ __launch_bounds__(256)
void split_x_kernel(const float* __restrict__ x)
{
    int idx4 = blockIdx.x * 256 + threadIdx.x;
    float4 v = ((const float4*)x)[idx4];
    uint32_t h0, l0, h1, l1;
    split2(v.x, v.y, h0, l0);
    split2(v.z, v.w, h1, l1);
    ((uint2*)g_Xh)[idx4] = make_uint2(h0, h1);
    ((uint2*)g_Xl)[idx4] = make_uint2(l0, l1);
}

__global__ __launch_bounds__(256)
void split_w_kernel(const float* __restrict__ Wq, const float* __restrict__ Wk,
                    const float* __restrict__ Wv, const float* __restrict__ Wo)
{
    int mode = blockIdx.x >> 8;
    const float* W = (mode == 0) ? Wq : (mode == 1) ? Wk : (mode == 2) ? Wv : Wo;
    int e = (blockIdx.x & 255) * 256 + threadIdx.x;
    int n = e >> 8, k = e & 255;
    float w = W[k * 256 + n];
    __nv_bfloat16 h = __float2bfloat16(w);
    float lo = w - __bfloat162float(h);
    g_Wth[mode * 65536 + e] = h;
    g_Wtl[mode * 65536 + e] = __float2bfloat16(lo);
}

// ---------------------------------------------------------------------------
// GEMM kernel (split-bf16 3-term, cp.async double-buffered, 128x64 tile,
// 256 threads): C[128x64] = A[128x256] @ Wt[64x256]^T
// ---------------------------------------------------------------------------
#define GBUF(i) ((uint32_t)(i) * 49152u)
#define GAH 0u
#define GAL 16384u
#define GBH 32768u
#define GBL 40960u
#define GEMM_SMEM 98304u

__device__ __forceinline__ void gemm_issue(uint32_t sb, int bufi, int kc,
                                           const __nv_bfloat16* Ah, const __nv_bfloat16* Al,
                                           const __nv_bfloat16* Bth, const __nv_bfloat16* Btl,
                                           int rowBase, int colBase, int tid)
{
    const uint32_t gb = sb + GBUF(bufi);
    #pragma unroll
    for (int i = 0; i < 4; i++) {          // A: 128 rows hi+lo
        int idx = tid + i * 256;
        int r = idx >> 3, seg = idx & 7;
        uint32_t so = sw128((uint32_t)(r * 128 + seg * 16));
        const size_t ao = (size_t)(rowBase + r) * 256 + kc * 64 + seg * 8;
        cp16(gb + GAH + so, Ah + ao);
        cp16(gb + GAL + so, Al + ao);
    }
    #pragma unroll
    for (int i = 0; i < 2; i++) {          // B: 64 rows hi+lo
        int idx = tid + i * 256;
        int r = idx >> 3, seg = idx & 7;
        uint32_t so = sw128((uint32_t)(r * 128 + seg * 16));
        const size_t bo = (size_t)(colBase + r) * 256 + kc * 64 + seg * 8;
        cp16(gb + GBH + so, Bth + bo);
        cp16(gb + GBL + so, Btl + bo);
    }
}

__global__ __launch_bounds__(256)
void gemm_kernel(int mode_base,
                 const float* __restrict__ bq, const float* __restrict__ bk,
                 const float* __restrict__ bv, const float* __restrict__ bo,
                 float* __restrict__ out)
{
    extern __shared__ char sm[];
    const uint32_t sb = smem_u32(sm);
    const int tid = threadIdx.x;
    const int wid = tid >> 5, lane = tid & 31;
    const int mode = mode_base + blockIdx.z;
    const int rowBase = blockIdx.y * 128;
    const int colBase = blockIdx.x * 64;

    const __nv_bfloat16* Ah = (mode < 3) ? g_Xh : g_AOh;
    const __nv_bfloat16* Al = (mode < 3) ? g_Xl : g_AOl;
    const __nv_bfloat16* Bth = g_Wth + mode * 65536;
    const __nv_bfloat16* Btl = g_Wtl + mode * 65536;
    const float* bias = (mode == 0) ? bq : (mode == 1) ? bk : (mode == 2) ? bv : bo;

    const int bnrow = (lane & 7) + ((lane >> 4) << 3);
    const int bkcol = ((lane >> 3) & 1) * 16;
    const uint32_t aoff_base = (uint32_t)((wid * 16 + (lane & 15)) * 128 + (lane >> 4) * 16);

    gemm_issue(sb, 0, 0, Ah, Al, Bth, Btl, rowBase, colBase, tid);
    CP_COMMIT();
    gemm_issue(sb, 1, 1, Ah, Al, Bth, Btl, rowBase, colBase, tid);
    CP_COMMIT();

    float sc[8][4] = {};

    for (int kc = 0; kc < 4; kc++) {
        if (kc < 3) {
            asm volatile("cp.async.wait_group 1;" ::: "memory");
        } else {
            asm volatile("cp.async.wait_group 0;" ::: "memory");
        }
        __syncthreads();

        const uint32_t gb = sb + GBUF(kc & 1);
        #pragma unroll
        for (int ks = 0; ks < 4; ks++) {
            uint32_t ah[4], al[4], kb[16], kbl[16];
            uint32_t aoff = sw128(aoff_base + ks * 32);
            ldsm4(ah, gb + GAH + aoff);
            ldsm4(al, gb + GAL + aoff);
            #pragma unroll
            for (int p = 0; p < 4; p++) {
                uint32_t off = sw128((uint32_t)((p * 16 + bnrow) * 128 + ks * 32 + bkcol));
                ldsm4(&kb[p * 4],  gb + GBH + off);
                ldsm4(&kbl[p * 4], gb + GBL + off);
            }
            #pragma unroll
            for (int j = 0; j < 8; j++) mma_bf16(sc[j], ah, &kb[j * 2]);
            #pragma unroll
            for (int j = 0; j < 8; j++) mma_bf16(sc[j], ah, &kbl[j * 2]);
            #pragma unroll
            for (int j = 0; j < 8; j++) mma_bf16(sc[j], al, &kb[j * 2]);
        }
        __syncthreads();

        if (kc + 2 < 4) {
            gemm_issue(sb, kc & 1, kc + 2, Ah, Al, Bth, Btl, rowBase, colBase, tid);
            CP_COMMIT();
        }
    }

    // ------------------ epilogues ------------------
    const int row0 = rowBase + wid * 16 + (lane >> 2);

    if (mode <= 1) {
        __half* dst = (mode == 0) ? g_Qf : g_Kf;
        #pragma unroll
        for (int j = 0; j < 8; j++) {
            int col0 = colBase + j * 8 + (lane & 3) * 2;
            int h = col0 >> 5, d0 = col0 & 31;
            float b0 = __ldg(&bias[col0]), b1 = __ldg(&bias[col0 + 1]);
            #pragma unroll
            for (int half = 0; half < 2; half++) {
                int row = row0 + half * 8;
                int bb = row >> 11, n = row & (Nx - 1);
                float v0 = sc[j][half * 2 + 0] + b0;
                float v1 = sc[j][half * 2 + 1] + b1;
                float sn0, cn0, sn1, cn1;
                __sincosf(v0, &sn0, &cn0);
                __sincosf(v1, &sn1, &cn1);
                size_t fb = ((size_t)(bb * Hx + h) * Nx + n) * Fx;
                *(uint32_t*)&dst[fb + d0]      = packh2(cn0 * CFOLD, cn1 * CFOLD);
                *(uint32_t*)&dst[fb + 32 + d0] = packh2(sn0 * CFOLD, sn1 * CFOLD);
            }
        }
    } else if (mode == 3) {
        #pragma unroll
        for (int j = 0; j < 8; j++) {
            int col0 = colBase + j * 8 + (lane & 3) * 2;
            float b0 = __ldg(&bias[col0]), b1 = __ldg(&bias[col0 + 1]);
            #pragma unroll
            for (int half = 0; half < 2; half++) {
                int row = row0 + half * 8;
                float2 v = make_float2(sc[j][half * 2 + 0] + b0, sc[j][half * 2 + 1] + b1);
                *(float2*)&out[(size_t)row * 256 + col0] = v;
            }
        }
    } else {
        // mode 2: V — fp16 single + smem transpose + store [bh][d][n]
        __syncthreads();
        __half* sv = (__half*)sm;           // [128][66] fp16 = 16.5KB
        #pragma unroll
        for (int j = 0; j < 8; j++) {
            int c0 = j * 8 + (lane & 3) * 2;
            float b0 = __ldg(&bias[colBase + c0]), b1 = __ldg(&bias[colBase + c0 + 1]);
            #pragma unroll
            for (int half = 0; half < 2; half++) {
                int mrow = wid * 16 + (lane >> 2) + half * 8;
                sv[mrow * 66 + c0]     = __float2half(sc[j][half * 2 + 0] + b0);
                sv[mrow * 66 + c0 + 1] = __float2half(sc[j][half * 2 + 1] + b1);
            }
        }
        __syncthreads();
        int d   = tid >> 2;                 // 0..63
        int nch = (tid & 3) * 32;           // 0,32,64,96
        int colg = colBase + d;
        int h = colg >> 5, dd = colg & 31;
        int bb = rowBase >> 11;
        int nt = (rowBase & (Nx - 1)) + nch;
        uint32_t ph[16];
        #pragma unroll
        for (int m = 0; m < 16; m++) {
            uint32_t a0 = *(const unsigned short*)&sv[(nch + 2 * m) * 66 + d];
            uint32_t a1 = *(const unsigned short*)&sv[(nch + 2 * m + 1) * 66 + d];
            ph[m] = a0 | (a1 << 16);
        }
        size_t base = ((size_t)((bb * Hx + h) * HDx + dd)) * Nx + nt;
        #pragma unroll
        for (int q = 0; q < 4; q++)
            *(uint4*)&g_Vtf[base + q * 8] = make_uint4(ph[q*4+0], ph[q*4+1], ph[q*4+2], ph[q*4+3]);
    }
}

// ---------------------------------------------------------------------------
// Attention: 2 heads per 256-thread CTA (warps 0-3 -> h0, 4-7 -> h1),
// shared fp32 topo tile. fp16 single-term S + PV, double-buffered cp.async.
// smem 80KB/CTA -> 2 CTAs/SM (16 warps/SM).
// ---------------------------------------------------------------------------
#define STG(i)    ((uint32_t)(i) * 40960u)
#define SK(i,hd)  (STG(i) + (uint32_t)(hd) * 8192u)
#define SV(i,hd)  (STG(i) + 16384u + (uint32_t)(hd) * 4096u)
#define ST(i)     (STG(i) + 24576u)
#define QSTAGE    24576u          /* stage0 topo region: Qh0 +0, Qh1 +8192 */
#define ATTN_SMEM 81920u

__device__ __forceinline__ void issue_kvt2(uint32_t sb, int i, int m0,
                                           const __half* Kf0, const __half* Kf1,
                                           const __half* Vf0, const __half* Vf1,
                                           const float* Tq, int tid)
{
    #pragma unroll
    for (int ii = 0; ii < 2; ii++) {       // K h0, K h1: 512 cp each
        int idx = tid + ii * 256;
        int r = idx >> 3, seg = idx & 7;
        uint32_t so = sw128((uint32_t)(r * 128 + seg * 16));
        cp16(sb + SK(i,0) + so, Kf0 + (size_t)(m0 + r) * Fx + seg * 8);
        cp16(sb + SK(i,1) + so, Kf1 + (size_t)(m0 + r) * Fx + seg * 8);
    }
    {                                       // V h0, V h1: 256 cp each
        int d = tid >> 3, seg = tid & 7;
        uint32_t so = sw128((uint32_t)(d * 128 + seg * 16));
        cp16(sb + SV(i,0) + so, Vf0 + (size_t)d * Nx + m0 + seg * 8);
        cp16(sb + SV(i,1) + so, Vf1 + (size_t)d * Nx + m0 + seg * 8);
    }
    // topo fp32: 64 rows x 256 bytes, row-XOR swizzle on 16B groups
    #pragma unroll
    for (int ii = 0; ii < 4; ii++) {
        int idx = tid + ii * 256;
        int r = idx >> 4, seg = idx & 15;
        uint32_t off = ((uint32_t)(seg * 16)) ^ (((uint32_t)(r & 7)) << 5);
        cp16(sb + ST(i) + (uint32_t)(r * 256) + off, Tq + (size_t)r * Nx + m0 + seg * 4);
    }
}

__global__ __launch_bounds__(256, 2)
void attn_kernel(const float* __restrict__ topo)
{
    extern __shared__ char sm[];
    const uint32_t sb = smem_u32(sm);

    const int tid  = threadIdx.x;
    const int wid  = tid >> 5;
    const int lane = tid & 31;
    const int hd   = wid >> 2;          // head within pair
    const int wq   = wid & 3;
    const int n0 = blockIdx.x * 64;
    const int b  = blockIdx.z;
    const int h0 = blockIdx.y * 2;
    const int bh0 = b * Hx + h0;
    const int qr0 = wq * 16;

    const __half* Kf0 = g_Kf + (size_t)bh0 * Nx * Fx;
    const __half* Kf1 = Kf0 + (size_t)Nx * Fx;
    const __half* Vf0 = g_Vtf + (size_t)bh0 * HDx * Nx;
    const __half* Vf1 = Vf0 + (size_t)HDx * Nx;
    const float*  Tq  = topo + ((size_t)b * Nx + n0) * Nx;
    const __half* Qme = g_Qf + ((size_t)(bh0 + hd) * Nx + n0) * Fx;

    // ---- prologue: both Q tiles via QSTAGE (stage0 topo region) ----
    {
        const __half* Q0 = g_Qf + ((size_t)bh0 * Nx + n0) * Fx;
        const __half* Q1 = Q0 + (size_t)Nx * Fx;
        #pragma unroll
        for (int ii = 0; ii < 2; ii++) {
            int idx = tid + ii * 256;
            int r = idx >> 3, seg = idx & 7;
            uint32_t so = sw128((uint32_t)(r * 128 + seg * 16));
            *(float4*)(sm + QSTAGE + so)         = *(const float4*)(Q0 + (size_t)r * Fx + seg * 8);
            *(float4*)(sm + QSTAGE + 8192u + so) = *(const float4*)(Q1 + (size_t)r * Fx + seg * 8);
        }
    }
    __syncthreads();
    uint32_t aQ[4][4];
    {
        const uint32_t qb = sb + QSTAGE + (uint32_t)hd * 8192u;
        int qrow = qr0 + (lane & 15);
        int colp = (lane >> 4) * 16;
        #pragma unroll
        for (int ks = 0; ks < 4; ks++) {
            uint32_t off = sw128((uint32_t)(qrow * 128 + ks * 32 + colp));
            ldsm4(aQ[ks], qb + off);
        }
    }
    __syncthreads();   // all warps done with QSTAGE before topo(0) overwrites

    issue_kvt2(sb, 0, 0,  Kf0, Kf1, Vf0, Vf1, Tq, tid);
    CP_COMMIT();
    issue_kvt2(sb, 1, 64, Kf0, Kf1, Vf0, Vf1, Tq, tid);
    CP_COMMIT();

    const int bnrow = (lane & 7) + ((lane >> 4) << 3);
    const int bkcol = ((lane >> 3) & 1) * 16;
    const int trow0 = qr0 + (lane >> 2);
    const uint32_t tcolb = (uint32_t)((lane & 3) * 8);
    const uint32_t txor  = ((uint32_t)(trow0 & 7)) << 5;

    float oc[4][4] = {};
    float lsum0 = 0.f, lsum1 = 0.f;

    for (int t = 0; t < NT; t++) {
        if (t < NT - 1) {
            asm volatile("cp.async.wait_group 1;" ::: "memory");
        } else {
            asm volatile("cp.async.wait_group 0;" ::: "memory");
        }
        __syncthreads();

        const int bi = t & 1;
        const uint32_t kbase = sb + SK(bi, hd);

        // ---- S = Qf . Kf^T (single fp16 term, SCL2 folded into features) ----
        float scr[8][4] = {};
        #pragma unroll
        for (int ks = 0; ks < 4; ks++) {
            #pragma unroll
            for (int p = 0; p < 4; p++) {
                uint32_t kb[4];
                uint32_t off = sw128((uint32_t)((p * 16 + bnrow) * 128 + ks * 32 + bkcol));
                ldsm4(kb, kbase + off);
                mma_fp16(scr[2*p],   aQ[ks], &kb[0]);
                mma_fp16(scr[2*p+1], aQ[ks], &kb[2]);
            }
        }

        // ---- fused epilogue (fp32 topo from smem) + single-term fp16 PV ----
        const uint32_t vbase = sb + SV(bi, hd);
        const uint32_t tbase = sb + ST(bi) + (uint32_t)(trow0 * 256);
        #pragma unroll
        for (int ks = 0; ks < 4; ks++) {
            uint32_t vb[8];
            #pragma unroll
            for (int p = 0; p < 2; p++) {
                uint32_t off = sw128((uint32_t)((p * 16 + bnrow) * 128 + ks * 32 + bkcol));
                ldsm4(&vb[p * 4], vbase + off);
            }
            uint32_t pH[4];
            #pragma unroll
            for (int jj = 0; jj < 2; jj++) {
                const int j = 2 * ks + jj;
                uint32_t a0 = tbase + (((uint32_t)(j * 32) + tcolb) ^ txor);
                float t0x, t0y, t1x, t1y;
                asm volatile("ld.shared.v2.f32 {%0,%1}, [%2];"
                    : "=f"(t0x), "=f"(t0y) : "r"(a0));
                asm volatile("ld.shared.v2.f32 {%0,%1}, [%2];"
                    : "=f"(t1x), "=f"(t1y) : "r"(a0 + 2048u));
                float p00 = exp2f(fmaf(scr[j][0], t0x, -SM2H));
                float p01 = exp2f(fmaf(scr[j][1], t0y, -SM2H));
                float p10 = exp2f(fmaf(scr[j][2], t1x, -SM2H));
                float p11 = exp2f(fmaf(scr[j][3], t1y, -SM2H));
                lsum0 += p00 + p01;
                lsum1 += p10 + p11;
                pH[jj*2 + 0] = packh2(p00, p01);
                pH[jj*2 + 1] = packh2(p10, p11);
            }
            #pragma unroll
            for (int jd = 0; jd < 4; jd++) mma_fp16(oc[jd], pH, &vb[jd * 2]);
        }
        __syncthreads();

        if (t + 2 < NT) {
            issue_kvt2(sb, bi, (t + 2) * 64, Kf0, Kf1, Vf0, Vf1, Tq, tid);
            CP_COMMIT();
        }
    }

    // finalize: reduce l over the quad, normalize (2^10 scale cancels), store
    lsum0 += __shfl_xor_sync(0xffffffffu, lsum0, 1);
    lsum0 += __shfl_xor_sync(0xffffffffu, lsum0, 2);
    lsum1 += __shfl_xor_sync(0xffffffffu, lsum1, 1);
    lsum1 += __shfl_xor_sync(0xffffffffu, lsum1, 2);
    const float inv0 = 1.0f / lsum0;
    const float inv1 = 1.0f / lsum1;

    const int r0 = n0 + qr0 + (lane >> 2);
    size_t base0 = ((size_t)(b * Nx + r0)) * DIMx + (h0 + hd) * HDx + (lane & 3) * 2;
    size_t base1 = base0 + 8 * DIMx;
    #pragma unroll
    for (int jd = 0; jd < 4; jd++) {
        uint32_t hp, lp;
        split2(oc[jd][0] * inv0, oc[jd][1] * inv0, hp, lp);
        *(uint32_t*)&g_AOh[base0 + jd * 8] = hp;
        *(uint32_t*)&g_AOl[base0 + jd * 8] = lp;
        split2(oc[jd][2] * inv1, oc[jd][3] * inv1, hp, lp);
        *(uint32_t*)&g_AOh[base1 + jd * 8] = hp;
        *(uint32_t*)&g_AOl[base1 + jd * 8] = lp;
    }
}

// ---------------------------------------------------------------------------
extern "C" void kernel_launch(void* const* d_in, const int* in_sizes, int n_in,
                              void* d_out, int out_size)
{
    const float* x    = (const float*)d_in[0];
    const float* topo = (const float*)d_in[1];
    const float* Wq   = (const float*)d_in[2];
    const float* bq   = (const float*)d_in[3];
    const float* Wk   = (const float*)d_in[4];
    const float* bk   = (const float*)d_in[5];
    const float* Wv   = (const float*)d_in[6];
    const float* bv   = (const float*)d_in[7];
    const float* Wo   = (const float*)d_in[8];
    const float* bo   = (const float*)d_in[9];
    float* out = (float*)d_out;
    (void)in_sizes; (void)n_in; (void)out_size;

    cudaFuncSetAttribute(attn_kernel,
                         cudaFuncAttributeMaxDynamicSharedMemorySize, ATTN_SMEM);
    cudaFuncSetAttribute(gemm_kernel,
                         cudaFuncAttributeMaxDynamicSharedMemorySize, GEMM_SMEM);

    split_x_kernel<<<2048, 256>>>(x);
    split_w_kernel<<<1024, 256>>>(Wq, Wk, Wv, Wo);

    dim3 gq(4, 64, 3);
    gemm_kernel<<<gq, 256, GEMM_SMEM>>>(0, bq, bk, bv, bo, out);

    dim3 ga(Nx / 64, Hx / 2, Bx);
    attn_kernel<<<ga, 256, ATTN_SMEM>>>(topo);

    dim3 go(4, 64, 1);
    gemm_kernel<<<go, 256, GEMM_SMEM>>>(3, bq, bk, bv, bo, out);
}

// round 15
// speedup vs baseline: 1.2196x; 1.2196x over previous
#include <cuda_runtime.h>
#include <cuda_bf16.h>
#include <cuda_fp16.h>
#include <math.h>
#include <stdint.h>

#define Bx 4
#define Nx 2048
#define DIMx 256
#define Hx 8
#define HDx 32
#define Fx 64
#define MTOT (Bx*Nx)
#define NT 32

// ------------------------- device scratch (no allocs) -----------------------
__device__ __nv_bfloat16 g_Xh[MTOT*DIMx];
__device__ __nv_bfloat16 g_Xl[MTOT*DIMx];
__device__ __nv_bfloat16 g_Wth[4*DIMx*DIMx];   // transposed weights [mode][n][k]
__device__ __nv_bfloat16 g_Wtl[4*DIMx*DIMx];
__device__ __half        g_Qf[Bx*Hx*Nx*Fx];     // fp16 features * sqrt(SCL2)
__device__ __half        g_Kf[Bx*Hx*Nx*Fx];
__device__ __half        g_Vtf[Bx*Hx*HDx*Nx];   // [bh][d][n], fp16
__device__ __nv_bfloat16 g_AOh[MTOT*DIMx];
__device__ __nv_bfloat16 g_AOl[MTOT*DIMx];

// ------------------------- helpers ------------------------------------------
__device__ __forceinline__ uint32_t smem_u32(const void* p) {
    uint32_t a;
    asm("{ .reg .u64 t; cvta.to.shared.u64 t, %1; cvt.u32.u64 %0, t; }" : "=r"(a) : "l"(p));
    return a;
}
__device__ __forceinline__ uint32_t packbf2(float lo, float hi) {
    uint32_t r;
    asm("cvt.rn.bf16x2.f32 %0, %1, %2;" : "=r"(r) : "f"(hi), "f"(lo));
    return r;
}
__device__ __forceinline__ void split2(float v0, float v1, uint32_t& hp, uint32_t& lp) {
    hp = packbf2(v0, v1);
    float h0 = __uint_as_float(hp << 16), h1 = __uint_as_float(hp & 0xffff0000u);
    lp = packbf2(v0 - h0, v1 - h1);
}
__device__ __forceinline__ uint32_t packh2(float lo, float hi) {
    uint32_t r;
    asm("cvt.rn.f16x2.f32 %0, %1, %2;" : "=r"(r) : "f"(hi), "f"(lo));
    return r;
}
__device__ __forceinline__ void ldsm4(uint32_t* r, uint32_t addr) {
    asm volatile("ldmatrix.sync.aligned.m8n8.x4.shared.b16 {%0,%1,%2,%3}, [%4];"
        : "=r"(r[0]), "=r"(r[1]), "=r"(r[2]), "=r"(r[3]) : "r"(addr));
}
__device__ __forceinline__ void mma_bf16(float* c, const uint32_t* a, const uint32_t* b) {
    asm volatile("mma.sync.aligned.m16n8k16.row.col.f32.bf16.bf16.f32 "
        "{%0,%1,%2,%3}, {%4,%5,%6,%7}, {%8,%9}, {%0,%1,%2,%3};"
        : "+f"(c[0]), "+f"(c[1]), "+f"(c[2]), "+f"(c[3])
        : "r"(a[0]), "r"(a[1]), "r"(a[2]), "r"(a[3]), "r"(b[0]), "r"(b[1]));
}
__device__ __forceinline__ void mma_fp16(float* c, const uint32_t* a, const uint32_t* b) {
    asm volatile("mma.sync.aligned.m16n8k16.row.col.f32.f16.f16.f32 "
        "{%0,%1,%2,%3}, {%4,%5,%6,%7}, {%8,%9}, {%0,%1,%2,%3};"
        : "+f"(c[0]), "+f"(c[1]), "+f"(c[2]), "+f"(c[3])
        : "r"(a[0]), "r"(a[1]), "r"(a[2]), "r"(a[3]), "r"(b[0]), "r"(b[1]));
}
__device__ __forceinline__ uint32_t sw128(uint32_t off) {
    return off ^ ((off >> 3) & 0x70);
}
__device__ __forceinline__ void cp16(uint32_t dst, const void* src) {
    asm volatile("cp.async.cg.shared.global [%0], [%1], 16;" :: "r"(dst), "l"(src) : "memory");
}
#define CP_COMMIT() asm volatile("cp.async.commit_group;" ::: "memory")

#define CFOLD 0.71420719f       /* sqrt((2/sqrt(32))*log2(e)) */
#define SM2H  6.4467223514f     /* 11.4*log2(e) - 10  (p scaled by 2^10) */

// ---------------------------------------------------------------------------
// Merged prep kernel: blocks [0, 2048) split X; blocks [2048, 3072) split W.
// Grid-stride not needed: exact coverage, one launch instead of two.
// ---------------------------------------------------------------------------
__global__ __launch_bounds__(256)
void prep_kernel(const float* __restrict__ x,
                 const float* __restrict__ Wq, const float* __restrict__ Wk,
                 const float* __restrict__ Wv, const float* __restrict__ Wo)
{
    int blk = blockIdx.x;
    if (blk < 2048) {
        int idx4 = blk * 256 + threadIdx.x;   // 524288 float4s
        float4 v = ((const float4*)x)[idx4];
        uint32_t h0, l0, h1, l1;
        split2(v.x, v.y, h0, l0);
        split2(v.z, v.w, h1, l1);
        ((uint2*)g_Xh)[idx4] = make_uint2(h0, h1);
        ((uint2*)g_Xl)[idx4] = make_uint2(l0, l1);
    } else {
        int wb = blk - 2048;                  // 0..1023
        int mode = wb >> 8;
        const float* W = (mode == 0) ? Wq : (mode == 1) ? Wk : (mode == 2) ? Wv : Wo;
        int e = (wb & 255) * 256 + threadIdx.x;  // 65536 per mode
        int n = e >> 8, k = e & 255;
        float w = W[k * 256 + n];
        __nv_bfloat16 h = __float2bfloat16(w);
        float lo = w - __bfloat162float(h);
        g_Wth[mode * 65536 + e] = h;
        g_Wtl[mode * 65536 + e] = __float2bfloat16(lo);
    }
}

// ---------------------------------------------------------------------------
// GEMM kernel (HMMA split-bf16 3-term, cp.async double-buffered k-chunks):
// C[64x64] = A[64x256] @ Wt[64x256]^T   (round-13 proven config)
// ---------------------------------------------------------------------------
#define GBUF(i) ((uint32_t)(i) * 32768u)
#define GAH 0u
#define GAL 8192u
#define GBH 16384u
#define GBL 24576u
#define GEMM_SMEM 65536u

__device__ __forceinline__ void gemm_issue(uint32_t sb, int bufi, int kc,
                                           const __nv_bfloat16* Ah, const __nv_bfloat16* Al,
                                           const __nv_bfloat16* Bth, const __nv_bfloat16* Btl,
                                           int rowBase, int colBase, int tid)
{
    const uint32_t gb = sb + GBUF(bufi);
    #pragma unroll
    for (int i = 0; i < 4; i++) {
        int idx = tid + i * 128;
        int r = idx >> 3, seg = idx & 7;
        uint32_t so = sw128((uint32_t)(r * 128 + seg * 16));
        const size_t ao = (size_t)(rowBase + r) * 256 + kc * 64 + seg * 8;
        const size_t bo = (size_t)(colBase + r) * 256 + kc * 64 + seg * 8;
        cp16(gb + GAH + so, Ah + ao);
        cp16(gb + GAL + so, Al + ao);
        cp16(gb + GBH + so, Bth + bo);
        cp16(gb + GBL + so, Btl + bo);
    }
}

__global__ __launch_bounds__(128)
void gemm_kernel(int mode_base,
                 const float* __restrict__ bq, const float* __restrict__ bk,
                 const float* __restrict__ bv, const float* __restrict__ bo,
                 float* __restrict__ out)
{
    extern __shared__ char sm[];
    const uint32_t sb = smem_u32(sm);
    const int tid = threadIdx.x;
    const int wid = tid >> 5, lane = tid & 31;
    const int mode = mode_base + blockIdx.z;
    const int rowBase = blockIdx.y * 64;
    const int colBase = blockIdx.x * 64;

    const __nv_bfloat16* Ah = (mode < 3) ? g_Xh : g_AOh;
    const __nv_bfloat16* Al = (mode < 3) ? g_Xl : g_AOl;
    const __nv_bfloat16* Bth = g_Wth + mode * 65536;
    const __nv_bfloat16* Btl = g_Wtl + mode * 65536;
    const float* bias = (mode == 0) ? bq : (mode == 1) ? bk : (mode == 2) ? bv : bo;

    const int bnrow = (lane & 7) + ((lane >> 4) << 3);
    const int bkcol = ((lane >> 3) & 1) * 16;
    const uint32_t aoff_base = (uint32_t)((wid * 16 + (lane & 15)) * 128 + (lane >> 4) * 16);

    gemm_issue(sb, 0, 0, Ah, Al, Bth, Btl, rowBase, colBase, tid);
    CP_COMMIT();
    gemm_issue(sb, 1, 1, Ah, Al, Bth, Btl, rowBase, colBase, tid);
    CP_COMMIT();

    float sc[8][4] = {};

    for (int kc = 0; kc < 4; kc++) {
        if (kc < 3) {
            asm volatile("cp.async.wait_group 1;" ::: "memory");
        } else {
            asm volatile("cp.async.wait_group 0;" ::: "memory");
        }
        __syncthreads();

        const uint32_t gb = sb + GBUF(kc & 1);
        #pragma unroll
        for (int ks = 0; ks < 4; ks++) {
            uint32_t ah[4], al[4], kb[16], kbl[16];
            uint32_t aoff = sw128(aoff_base + ks * 32);
            ldsm4(ah, gb + GAH + aoff);
            ldsm4(al, gb + GAL + aoff);
            #pragma unroll
            for (int p = 0; p < 4; p++) {
                uint32_t off = sw128((uint32_t)((p * 16 + bnrow) * 128 + ks * 32 + bkcol));
                ldsm4(&kb[p * 4],  gb + GBH + off);
                ldsm4(&kbl[p * 4], gb + GBL + off);
            }
            #pragma unroll
            for (int j = 0; j < 8; j++) mma_bf16(sc[j], ah, &kb[j * 2]);
            #pragma unroll
            for (int j = 0; j < 8; j++) mma_bf16(sc[j], ah, &kbl[j * 2]);
            #pragma unroll
            for (int j = 0; j < 8; j++) mma_bf16(sc[j], al, &kb[j * 2]);
        }
        __syncthreads();

        if (kc + 2 < 4) {
            gemm_issue(sb, kc & 1, kc + 2, Ah, Al, Bth, Btl, rowBase, colBase, tid);
            CP_COMMIT();
        }
    }

    // ------------------ epilogues ------------------
    const int row0 = rowBase + wid * 16 + (lane >> 2);

    if (mode <= 1) {
        __half* dst = (mode == 0) ? g_Qf : g_Kf;
        #pragma unroll
        for (int j = 0; j < 8; j++) {
            int col0 = colBase + j * 8 + (lane & 3) * 2;
            int h = col0 >> 5, d0 = col0 & 31;
            float b0 = __ldg(&bias[col0]), b1 = __ldg(&bias[col0 + 1]);
            #pragma unroll
            for (int half = 0; half < 2; half++) {
                int row = row0 + half * 8;
                int bb = row >> 11, n = row & (Nx - 1);
                float v0 = sc[j][half * 2 + 0] + b0;
                float v1 = sc[j][half * 2 + 1] + b1;
                float sn0, cn0, sn1, cn1;
                __sincosf(v0, &sn0, &cn0);
                __sincosf(v1, &sn1, &cn1);
                size_t fb = ((size_t)(bb * Hx + h) * Nx + n) * Fx;
                *(uint32_t*)&dst[fb + d0]      = packh2(cn0 * CFOLD, cn1 * CFOLD);
                *(uint32_t*)&dst[fb + 32 + d0] = packh2(sn0 * CFOLD, sn1 * CFOLD);
            }
        }
    } else if (mode == 3) {
        #pragma unroll
        for (int j = 0; j < 8; j++) {
            int col0 = colBase + j * 8 + (lane & 3) * 2;
            float b0 = __ldg(&bias[col0]), b1 = __ldg(&bias[col0 + 1]);
            #pragma unroll
            for (int half = 0; half < 2; half++) {
                int row = row0 + half * 8;
                float2 v = make_float2(sc[j][half * 2 + 0] + b0, sc[j][half * 2 + 1] + b1);
                *(float2*)&out[(size_t)row * 256 + col0] = v;
            }
        }
    } else {
        // mode 2: V — fp16 single + smem transpose + store [bh][d][n]
        __syncthreads();
        __half* sv = (__half*)sm;           // [64][66]
        #pragma unroll
        for (int j = 0; j < 8; j++) {
            int c0 = j * 8 + (lane & 3) * 2;
            float b0 = __ldg(&bias[colBase + c0]), b1 = __ldg(&bias[colBase + c0 + 1]);
            #pragma unroll
            for (int half = 0; half < 2; half++) {
                int mrow = wid * 16 + (lane >> 2) + half * 8;
                sv[mrow * 66 + c0]     = __float2half(sc[j][half * 2 + 0] + b0);
                sv[mrow * 66 + c0 + 1] = __float2half(sc[j][half * 2 + 1] + b1);
            }
        }
        __syncthreads();
        int d   = tid >> 1;
        int nch = (tid & 1) * 32;
        int colg = colBase + d;
        int h = colg >> 5, dd = colg & 31;
        int bb = rowBase >> 11;
        int nt = (rowBase & (Nx - 1)) + nch;
        uint32_t ph[16];
        #pragma unroll
        for (int m = 0; m < 16; m++) {
            uint32_t a0 = *(const unsigned short*)&sv[(nch + 2 * m) * 66 + d];
            uint32_t a1 = *(const unsigned short*)&sv[(nch + 2 * m + 1) * 66 + d];
            ph[m] = a0 | (a1 << 16);
        }
        size_t base = ((size_t)((bb * Hx + h) * HDx + dd)) * Nx + nt;
        #pragma unroll
        for (int q = 0; q < 4; q++)
            *(uint4*)&g_Vtf[base + q * 8] = make_uint4(ph[q*4+0], ph[q*4+1], ph[q*4+2], ph[q*4+3]);
    }
}

// ---------------------------------------------------------------------------
// Attention (round-13 proven config): fp16 single-term S + PV; K/V fp16 +
// topo fp32 all cp.async double-buffered; 128 threads, 4 CTAs/SM, 56KB smem.
// ---------------------------------------------------------------------------
#define BUFK(i) ((uint32_t)(i) * 28672u)
#define BUFV(i) (BUFK(i) + 8192u)
#define BUFT(i) (BUFK(i) + 12288u)
#define QSTAGE  12288u
#define ATTN_SMEM 57344u

__device__ __forceinline__ void issue_kvt(uint32_t sb, int i, int m0,
                                          const __half* Kf, const __half* Vf,
                                          const float* Tq, int tid)
{
    #pragma unroll
    for (int ii = 0; ii < 4; ii++) {
        int idx = tid + ii * 128;
        int r = idx >> 3, seg = idx & 7;
        uint32_t so = sw128((uint32_t)(r * 128 + seg * 16));
        cp16(sb + BUFK(i) + so, Kf + (size_t)(m0 + r) * Fx + seg * 8);
    }
    #pragma unroll
    for (int ii = 0; ii < 2; ii++) {
        int idx = tid + ii * 128;
        int d = idx >> 3, seg = idx & 7;
        uint32_t so = sw128((uint32_t)(d * 128 + seg * 16));
        cp16(sb + BUFV(i) + so, Vf + (size_t)d * Nx + m0 + seg * 8);
    }
    // topo fp32: 64 rows x 256 bytes, row-XOR swizzle on 16B groups
    #pragma unroll
    for (int ii = 0; ii < 8; ii++) {
        int idx = tid + ii * 128;
        int r = idx >> 4, seg = idx & 15;
        uint32_t off = ((uint32_t)(seg * 16)) ^ (((uint32_t)(r & 7)) << 5);
        cp16(sb + BUFT(i) + (uint32_t)(r * 256) + off, Tq + (size_t)r * Nx + m0 + seg * 4);
    }
}

__global__ __launch_bounds__(128, 4)
void attn_kernel(const float* __restrict__ topo)
{
    extern __shared__ char sm[];
    const uint32_t sb = smem_u32(sm);

    const int tid  = threadIdx.x;
    const int wid  = tid >> 5;
    const int lane = tid & 31;
    const int n0 = blockIdx.x * 64;
    const int h  = blockIdx.y, b = blockIdx.z;
    const int bh = b * Hx + h;
    const int qr0 = wid * 16;

    const __half* Qf = g_Qf + ((size_t)bh * Nx + n0) * Fx;
    const __half* Kf = g_Kf + (size_t)bh * Nx * Fx;
    const __half* Vf = g_Vtf + (size_t)bh * HDx * Nx;
    const float*  Tq = topo + ((size_t)b * Nx + n0) * Nx;

    // ---- prologue: Q via QSTAGE (BUF0 topo region), then KVT prefetch ----
    #pragma unroll
    for (int i = 0; i < 4; i++) {
        int idx = tid + i * 128;
        int r = idx >> 3, seg = idx & 7;
        uint32_t so = sw128((uint32_t)(r * 128 + seg * 16));
        *(float4*)(sm + QSTAGE + so) = *(const float4*)(Qf + (size_t)r * Fx + seg * 8);
    }
    __syncthreads();
    uint32_t aQ[4][4];
    {
        int qrow = qr0 + (lane & 15);
        int colp = (lane >> 4) * 16;
        #pragma unroll
        for (int ks = 0; ks < 4; ks++) {
            uint32_t off = sw128((uint32_t)(qrow * 128 + ks * 32 + colp));
            ldsm4(aQ[ks], sb + QSTAGE + off);
        }
    }
    __syncthreads();   // all warps done reading QSTAGE before topo(0) overwrites

    issue_kvt(sb, 0, 0,  Kf, Vf, Tq, tid);
    CP_COMMIT();
    issue_kvt(sb, 1, 64, Kf, Vf, Tq, tid);
    CP_COMMIT();

    const int bnrow = (lane & 7) + ((lane >> 4) << 3);
    const int bkcol = ((lane >> 3) & 1) * 16;
    const int trow0 = qr0 + (lane >> 2);
    const uint32_t tcolb = (uint32_t)((lane & 3) * 8);
    const uint32_t txor  = ((uint32_t)(trow0 & 7)) << 5;

    float oc[4][4] = {};
    float lsum0 = 0.f, lsum1 = 0.f;

    for (int t = 0; t < NT; t++) {
        if (t < NT - 1) {
            asm volatile("cp.async.wait_group 1;" ::: "memory");
        } else {
            asm volatile("cp.async.wait_group 0;" ::: "memory");
        }
        __syncthreads();

        const int bi = t & 1;

        // ---- S = Qf . Kf^T (single fp16 term, SCL2 folded into features) ----
        float scr[8][4] = {};
        #pragma unroll
        for (int ks = 0; ks < 4; ks++) {
            #pragma unroll
            for (int p = 0; p < 4; p++) {
                uint32_t kb[4];
                uint32_t off = sw128((uint32_t)((p * 16 + bnrow) * 128 + ks * 32 + bkcol));
                ldsm4(kb, sb + BUFK(bi) + off);
                mma_fp16(scr[2*p],   aQ[ks], &kb[0]);
                mma_fp16(scr[2*p+1], aQ[ks], &kb[2]);
            }
        }

        // ---- fused epilogue (fp32 topo from smem) + single-term fp16 PV ----
        const uint32_t vbase = sb + BUFV(bi);
        const uint32_t tbase = sb + BUFT(bi) + (uint32_t)(trow0 * 256);
        #pragma unroll
        for (int ks = 0; ks < 4; ks++) {
            uint32_t vb[8];
            #pragma unroll
            for (int p = 0; p < 2; p++) {
                uint32_t off = sw128((uint32_t)((p * 16 + bnrow) * 128 + ks * 32 + bkcol));
                ldsm4(&vb[p * 4], vbase + off);
            }
            uint32_t pH[4];
            #pragma unroll
            for (int jj = 0; jj < 2; jj++) {
                const int j = 2 * ks + jj;
                uint32_t a0 = tbase + (((uint32_t)(j * 32) + tcolb) ^ txor);
                float t0x, t0y, t1x, t1y;
                asm volatile("ld.shared.v2.f32 {%0,%1}, [%2];"
                    : "=f"(t0x), "=f"(t0y) : "r"(a0));
                asm volatile("ld.shared.v2.f32 {%0,%1}, [%2];"
                    : "=f"(t1x), "=f"(t1y) : "r"(a0 + 2048u));
                float p00 = exp2f(fmaf(scr[j][0], t0x, -SM2H));
                float p01 = exp2f(fmaf(scr[j][1], t0y, -SM2H));
                float p10 = exp2f(fmaf(scr[j][2], t1x, -SM2H));
                float p11 = exp2f(fmaf(scr[j][3], t1y, -SM2H));
                lsum0 += p00 + p01;
                lsum1 += p10 + p11;
                pH[jj*2 + 0] = packh2(p00, p01);
                pH[jj*2 + 1] = packh2(p10, p11);
            }
            #pragma unroll
            for (int jd = 0; jd < 4; jd++) mma_fp16(oc[jd], pH, &vb[jd * 2]);
        }
        __syncthreads();

        if (t + 2 < NT) {
            issue_kvt(sb, bi, (t + 2) * 64, Kf, Vf, Tq, tid);
            CP_COMMIT();
        }
    }

    // finalize: reduce l over the quad, normalize (2^10 scale cancels), store
    lsum0 += __shfl_xor_sync(0xffffffffu, lsum0, 1);
    lsum0 += __shfl_xor_sync(0xffffffffu, lsum0, 2);
    lsum1 += __shfl_xor_sync(0xffffffffu, lsum1, 1);
    lsum1 += __shfl_xor_sync(0xffffffffu, lsum1, 2);
    const float inv0 = 1.0f / lsum0;
    const float inv1 = 1.0f / lsum1;

    const int r0 = n0 + qr0 + (lane >> 2);
    size_t base0 = ((size_t)(b * Nx + r0)) * DIMx + h * HDx + (lane & 3) * 2;
    size_t base1 = base0 + 8 * DIMx;
    #pragma unroll
    for (int jd = 0; jd < 4; jd++) {
        uint32_t hp, lp;
        split2(oc[jd][0] * inv0, oc[jd][1] * inv0, hp, lp);
        *(uint32_t*)&g_AOh[base0 + jd * 8] = hp;
        *(uint32_t*)&g_AOl[base0 + jd * 8] = lp;
        split2(oc[jd][2] * inv1, oc[jd][3] * inv1, hp, lp);
        *(uint32_t*)&g_AOh[base1 + jd * 8] = hp;
        *(uint32_t*)&g_AOl[base1 + jd * 8] = lp;
    }
}

// ---------------------------------------------------------------------------
extern "C" void kernel_launch(void* const* d_in, const int* in_sizes, int n_in,
                              void* d_out, int out_size)
{
    const float* x    = (const float*)d_in[0];
    const float* topo = (const float*)d_in[1];
    const float* Wq   = (const float*)d_in[2];
    const float* bq   = (const float*)d_in[3];
    const float* Wk   = (const float*)d_in[4];
    const float* bk   = (const float*)d_in[5];
    const float* Wv   = (const float*)d_in[6];
    const float* bv   = (const float*)d_in[7];
    const float* Wo   = (const float*)d_in[8];
    const float* bo   = (const float*)d_in[9];
    float* out = (float*)d_out;
    (void)in_sizes; (void)n_in; (void)out_size;

    cudaFuncSetAttribute(attn_kernel,
                         cudaFuncAttributeMaxDynamicSharedMemorySize, ATTN_SMEM);
    cudaFuncSetAttribute(gemm_kernel,
                         cudaFuncAttributeMaxDynamicSharedMemorySize, GEMM_SMEM);

    prep_kernel<<<3072, 256>>>(x, Wq, Wk, Wv, Wo);

    dim3 gq(4, 128, 3);
    gemm_kernel<<<gq, 128, GEMM_SMEM>>>(0, bq, bk, bv, bo, out);

    dim3 ga(Nx / 64, Hx, Bx);
    attn_kernel<<<ga, 128, ATTN_SMEM>>>(topo);

    dim3 go(4, 128, 1);
    gemm_kernel<<<go, 128, GEMM_SMEM>>>(3, bq, bk, bv, bo, out);
}